// round 10
// baseline (speedup 1.0000x reference)
#include <cuda_runtime.h>
#include <cuda_bf16.h>
#include <math.h>
#include <stdint.h>

#define Nn 128
#define Tt 256
#define Dd 1024
#define Hh 1024
#define G4 4096
#define Pp 196
#define KR 2048   // recurrent K: [h | attn]
#define MX (Nn * Tt)

// ================= device scratch (static) =================
__device__ __align__(16) __nv_bfloat16 g_Wxh[(size_t)G4 * Dd];
__device__ __align__(16) __nv_bfloat16 g_Wxl[(size_t)G4 * Dd];
__device__ __align__(16) __nv_bfloat16 g_Wfh[(size_t)G4 * KR];
__device__ __align__(16) __nv_bfloat16 g_Wfl[(size_t)G4 * KR];
__device__ __align__(16) __nv_bfloat16 g_xh[(size_t)MX * Dd];
__device__ __align__(16) __nv_bfloat16 g_xl[(size_t)MX * Dd];
__device__ float g_xp[(size_t)MX * G4];
__device__ __align__(16) __nv_bfloat16 g_acth[(size_t)Nn * KR];
__device__ __align__(16) __nv_bfloat16 g_actl[(size_t)Nn * KR];
__device__ float g_bf[G4];
__device__ float g_hnewT[Hh * Nn];
__device__ float g_cT[Hh * Nn];

// ================= helpers =================
__device__ __forceinline__ uint32_t smem_u32(const void* p) {
    uint32_t a;
    asm("{ .reg .u64 t; cvta.to.shared.u64 t, %1; cvt.u32.u64 %0, t; }" : "=r"(a) : "l"(p));
    return a;
}
__device__ __forceinline__ void cp16(uint32_t dst, const void* src) {
    asm volatile("cp.async.cg.shared.global [%0], [%1], 16;" :: "r"(dst), "l"(src));
}
__device__ __forceinline__ void cpcommit() { asm volatile("cp.async.commit_group;" ::: "memory"); }
template <int N> __device__ __forceinline__ void cpwait() {
    asm volatile("cp.async.wait_group %0;" :: "n"(N) : "memory");
}
__device__ __forceinline__ void ldsm_x4(uint32_t& r0, uint32_t& r1, uint32_t& r2, uint32_t& r3,
                                        uint32_t addr) {
    asm volatile("ldmatrix.sync.aligned.m8n8.x4.shared.b16 {%0,%1,%2,%3}, [%4];"
                 : "=r"(r0), "=r"(r1), "=r"(r2), "=r"(r3) : "r"(addr));
}
__device__ __forceinline__ void mma16816(float* d, const uint32_t* a, const uint32_t* b) {
    asm volatile(
        "mma.sync.aligned.m16n8k16.row.col.f32.bf16.bf16.f32 "
        "{%0,%1,%2,%3}, {%4,%5,%6,%7}, {%8,%9}, {%0,%1,%2,%3};"
        : "+f"(d[0]), "+f"(d[1]), "+f"(d[2]), "+f"(d[3])
        : "r"(a[0]), "r"(a[1]), "r"(a[2]), "r"(a[3]), "r"(b[0]), "r"(b[1]));
}
#define SWZ64(o) ((o) ^ (((o) >> 3) & 0x30))

__device__ __forceinline__ void bf16split(float v, __nv_bfloat16* hi, __nv_bfloat16* lo) {
    __nv_bfloat16 h = __float2bfloat16(v);
    *hi = h;
    *lo = __float2bfloat16(v - __bfloat162float(h));
}

// ================= one-time kernels =================
__global__ __launch_bounds__(256) void permute_kernel(
    const float* __restrict__ Wx, const float* __restrict__ Wh,
    const float* __restrict__ Wa, const float* __restrict__ b) {
    size_t total = (size_t)G4 * 3072;
    size_t stride = (size_t)gridDim.x * blockDim.x;
    for (size_t idx = (size_t)blockIdx.x * blockDim.x + threadIdx.x; idx < total; idx += stride) {
        int j = (int)(idx / 3072);
        int k = (int)(idx - (size_t)j * 3072);
        int src = (j & 3) * 1024 + (j >> 2);
        __nv_bfloat16 hi, lo;
        if (k < 1024) {
            bf16split(Wx[(size_t)k * G4 + src], &hi, &lo);
            g_Wxh[(size_t)j * Dd + k] = hi;
            g_Wxl[(size_t)j * Dd + k] = lo;
        } else {
            float v = (k < 2048) ? Wh[(size_t)(k - 1024) * G4 + src]
                                 : Wa[(size_t)(k - 2048) * G4 + src];
            bf16split(v, &hi, &lo);
            g_Wfh[(size_t)j * KR + (k - 1024)] = hi;
            g_Wfl[(size_t)j * KR + (k - 1024)] = lo;
        }
        if (k == 0) g_bf[j] = b[src];
    }
}

__global__ __launch_bounds__(256) void xsplit_kernel(const float* __restrict__ x) {
    size_t total = (size_t)MX * Dd;
    size_t stride = (size_t)gridDim.x * blockDim.x;
    for (size_t i = (size_t)blockIdx.x * blockDim.x + threadIdx.x; i < total; i += stride) {
        __nv_bfloat16 hi, lo;
        bf16split(x[i], &hi, &lo);
        g_xh[i] = hi;
        g_xl[i] = lo;
    }
}

__global__ __launch_bounds__(256) void init_kernel(const float* __restrict__ A) {
    int n = blockIdx.x;
    for (int u = threadIdx.x; u < Hh; u += blockDim.x) {
        const float4* r = (const float4*)(A + ((size_t)n * Hh + u) * Pp);
        float s = 0.f;
#pragma unroll
        for (int i = 0; i < 49; i++) {
            float4 v = r[i];
            s += v.x + v.y + v.z + v.w;
        }
        float m = s * (1.f / 196.f);
        g_hnewT[u * Nn + n] = m;
        g_cT[u * Nn + n] = m;
    }
}

// ================= generic split-bf16x3 mma mainloop =================
#define KC 32
#define STB 20480
#define NSTG 3

__device__ __forceinline__ void load_chunk_g(
    int tid, int c, char* buf,
    const __nv_bfloat16* Ah, const __nv_bfloat16* Al, int lda,
    const __nv_bfloat16* Bh, const __nv_bfloat16* Bl, int ldb) {
    uint32_t sbase = smem_u32(buf);
#pragma unroll
    for (int it = 0; it < 2; it++) {
        int id = tid + it * 256;
        int m = id >> 2, kc = id & 3;
        uint32_t off = SWZ64((uint32_t)m * 64 + (uint32_t)kc * 16);
        size_t gidx = (size_t)m * lda + (size_t)c * KC + kc * 8;
        cp16(sbase + off, Ah + gidx);
        cp16(sbase + 8192 + off, Al + gidx);
    }
    if (tid < 128) {
        int nrow = tid >> 2, kc = tid & 3;
        uint32_t off = SWZ64((uint32_t)nrow * 64 + (uint32_t)kc * 16);
        size_t gidx = (size_t)nrow * ldb + (size_t)c * KC + kc * 8;
        cp16(sbase + 16384 + off, Bh + gidx);
        cp16(sbase + 18432 + off, Bl + gidx);
    }
    cpcommit();
}

__device__ __forceinline__ void mma_mainloop(
    int tid, char* dsm, float acc[4][4], int nch,
    const __nv_bfloat16* Ah, const __nv_bfloat16* Al, int lda,
    const __nv_bfloat16* Bh, const __nv_bfloat16* Bl, int ldb) {
    int w = tid >> 5, lane = tid & 31;
    load_chunk_g(tid, 0, dsm, Ah, Al, lda, Bh, Bl, ldb);
    load_chunk_g(tid, 1, dsm + STB, Ah, Al, lda, Bh, Bl, ldb);
    for (int c = 0; c < nch; c++) {
        if (c + 1 < nch) cpwait<1>(); else cpwait<0>();
        __syncthreads();
        uint32_t sbase = smem_u32(dsm + (c % NSTG) * STB);
        int arow = w * 16 + (lane & 15);
#pragma unroll
        for (int ks = 0; ks < 2; ks++) {
            int ak = ks * 16 + ((lane & 16) ? 8 : 0);
            uint32_t aoff = SWZ64((uint32_t)arow * 64 + (uint32_t)ak * 2);
            uint32_t ah[4], al[4];
            ldsm_x4(ah[0], ah[1], ah[2], ah[3], sbase + aoff);
            ldsm_x4(al[0], al[1], al[2], al[3], sbase + 8192 + aoff);
            uint32_t bh[8], bl[8];
            int bk = ks * 16 + ((lane & 8) ? 8 : 0);
#pragma unroll
            for (int jj = 0; jj < 2; jj++) {
                int nrow = jj * 16 + ((lane & 16) ? 8 : 0) + (lane & 7);
                uint32_t boff = SWZ64((uint32_t)nrow * 64 + (uint32_t)bk * 2);
                ldsm_x4(bh[4 * jj], bh[4 * jj + 1], bh[4 * jj + 2], bh[4 * jj + 3],
                        sbase + 16384 + boff);
                ldsm_x4(bl[4 * jj], bl[4 * jj + 1], bl[4 * jj + 2], bl[4 * jj + 3],
                        sbase + 18432 + boff);
            }
#pragma unroll
            for (int j = 0; j < 4; j++) {
                mma16816(acc[j], ah, &bh[2 * j]);
                mma16816(acc[j], ah, &bl[2 * j]);
                mma16816(acc[j], al, &bh[2 * j]);
            }
        }
        if (c + 2 < nch)
            load_chunk_g(tid, c + 2, dsm + ((c + 2) % NSTG) * STB, Ah, Al, lda, Bh, Bl, ldb);
    }
}

// ================= one-time: xproj = x @ Wx + b =================
__global__ __launch_bounds__(256) void xproj_kernel() {
    extern __shared__ __align__(1024) char dsm[];
    int tid = threadIdx.x;
    int w = tid >> 5, lane = tid & 31;
    int j0 = blockIdx.x * 32;
    int m0 = blockIdx.y * 128;

    float acc[4][4];
#pragma unroll
    for (int j = 0; j < 4; j++)
#pragma unroll
        for (int r = 0; r < 4; r++) acc[j][r] = 0.f;

    mma_mainloop(tid, dsm, acc, Dd / KC,
                 g_xh + (size_t)m0 * Dd, g_xl + (size_t)m0 * Dd, Dd,
                 g_Wxh + (size_t)j0 * Dd, g_Wxl + (size_t)j0 * Dd, Dd);

    int row0 = m0 + w * 16 + (lane >> 2);
#pragma unroll
    for (int j = 0; j < 4; j++) {
        int col = j0 + j * 8 + (lane & 3) * 2;
        float2 bb = *(const float2*)&g_bf[col];
        *(float2*)&g_xp[(size_t)row0 * G4 + col] = make_float2(acc[j][0] + bb.x, acc[j][1] + bb.y);
        *(float2*)&g_xp[(size_t)(row0 + 8) * G4 + col] = make_float2(acc[j][2] + bb.x, acc[j][3] + bb.y);
    }
}

// ================= fused attention: one pass over A (flash-style) =================
// 128 blocks (one per n), 1024 threads. 7 p-tiles of 28.
// smem: T[28][1033] transposed tile; hsh[1024]; spart[32][28]; esh[28]; ctl[8]
#define PT 28
#define NTIL 7
#define TS 1033
#define ATT_SMEM ((PT * TS + 1024 + 32 * PT + PT + 8) * 4)

__global__ __launch_bounds__(1024) void attn_fused_kernel(const float* __restrict__ A, int t) {
    extern __shared__ float sm[];
    float* T = sm;                       // PT*TS
    float* hsh = sm + PT * TS;           // 1024
    float* spart = hsh + 1024;           // 32*PT
    float* esh = spart + 32 * PT;        // PT
    float* ctl = esh + PT;               // [0]=rescale, [1]=1/l

    int n = blockIdx.x;
    int tid = threadIdx.x;
    int w = tid >> 5, lane = tid & 31;

    // load h column (transposed state), commit bf16 split
    float hv = g_hnewT[tid * Nn + n];
    hsh[tid] = hv;
    {
        __nv_bfloat16 hi, lo;
        bf16split(hv, &hi, &lo);
        g_acth[(size_t)n * KR + tid] = hi;
        g_actl[(size_t)n * KR + tid] = lo;
    }
    float acc = 0.f;
    float m_run = -3.4e38f, l_run = 0.f;   // meaningful in warp 0 only
    __syncthreads();

    const float* An = A + (size_t)n * Hh * Pp;
    for (int tile = 0; tile < NTIL; tile++) {
        int p0 = tile * PT;
        // load tile (transposed) + per-lane partial scores
        float sp = 0.f;
        if (lane < PT) {
#pragma unroll 8
            for (int j = 0; j < 32; j++) {
                int u = w + 32 * j;
                float v = An[(size_t)u * Pp + p0 + lane];
                T[lane * TS + u] = v;
                sp += v * hsh[u];
            }
            spart[w * PT + lane] = sp;
        }
        __syncthreads();

        // warp 0: reduce partial scores, online softmax update
        if (w == 0) {
            float s = -3.4e38f;
            if (lane < PT) {
                float acc_s = 0.f;
#pragma unroll 8
                for (int k = 0; k < 32; k++) acc_s += spart[k * PT + lane];
                s = acc_s * 0.03125f;
            }
            float tm = s;
#pragma unroll
            for (int o = 16; o > 0; o >>= 1) tm = fmaxf(tm, __shfl_xor_sync(0xffffffff, tm, o));
            float m_new = fmaxf(m_run, tm);
            float r = expf(m_run - m_new);
            float e = (lane < PT) ? expf(s - m_new) : 0.f;
            float es = e;
#pragma unroll
            for (int o = 16; o > 0; o >>= 1) es += __shfl_xor_sync(0xffffffff, es, o);
            l_run = l_run * r + es;
            m_run = m_new;
            if (lane < PT) esh[lane] = e;
            if (lane == 0) ctl[0] = r;
        }
        __syncthreads();

        // thread-per-u accumulate
        float r = ctl[0];
        float a2 = 0.f;
#pragma unroll
        for (int p = 0; p < PT; p++) a2 += esh[p] * T[p * TS + tid];
        acc = acc * r + a2;
        __syncthreads();   // protect T/spart/esh before next tile
    }

    if (tid == 0) ctl[1] = 1.f / l_run;
    __syncthreads();
    float attn = acc * ctl[1];
    __nv_bfloat16 hi, lo;
    bf16split(attn, &hi, &lo);
    g_acth[(size_t)n * KR + 1024 + tid] = hi;
    g_actl[(size_t)n * KR + 1024 + tid] = lo;
}

// ================= gates: [h|attn]@Wf + xproj_t, fused LSTM =================
__global__ __launch_bounds__(256) void gates_mma_kernel(float* __restrict__ out, int t) {
    extern __shared__ __align__(1024) char dsm[];
    int tid = threadIdx.x;
    int w = tid >> 5, lane = tid & 31;
    int j0 = blockIdx.x * 32;

    float acc[4][4];
    {
        int row0 = w * 16 + (lane >> 2);
#pragma unroll
        for (int j = 0; j < 4; j++) {
            int col = j0 + j * 8 + (lane & 3) * 2;
            float2 v0 = __ldcs((const float2*)&g_xp[((size_t)row0 * Tt + t) * G4 + col]);
            float2 v1 = __ldcs((const float2*)&g_xp[((size_t)(row0 + 8) * Tt + t) * G4 + col]);
            acc[j][0] = v0.x; acc[j][1] = v0.y; acc[j][2] = v1.x; acc[j][3] = v1.y;
        }
    }

    mma_mainloop(tid, dsm, acc, KR / KC,
                 g_acth, g_actl, KR,
                 g_Wfh + (size_t)j0 * KR, g_Wfl + (size_t)j0 * KR, KR);

    int q = lane & 3;
    int rbase = w * 16 + (lane >> 2);
#pragma unroll
    for (int j = 0; j < 4; j++) {
        float e0 = __shfl_xor_sync(0xffffffff, acc[j][0], 1);
        float e1 = __shfl_xor_sync(0xffffffff, acc[j][1], 1);
        float e2 = __shfl_xor_sync(0xffffffff, acc[j][2], 1);
        float e3 = __shfl_xor_sync(0xffffffff, acc[j][3], 1);
        int u = blockIdx.x * 8 + 2 * j + (q >> 1);
        int m;
        float ai, af, ao, ag;
        if ((q & 1) == 0) {
            m = rbase;
            ai = acc[j][0]; af = acc[j][1]; ao = e0; ag = e1;
        } else {
            m = rbase + 8;
            ai = e2; af = e3; ao = acc[j][2]; ag = acc[j][3];
        }
        float ig = 1.f / (1.f + expf(-ai));
        float fg = 1.f / (1.f + expf(-af));
        float og = 1.f / (1.f + expf(-ao));
        float gg = tanhf(ag);
        float cn = fg * g_cT[u * Nn + m] + ig * gg;
        float hn = og * tanhf(cn);
        g_cT[u * Nn + m] = cn;
        g_hnewT[u * Nn + m] = hn;
        __stcs(&out[((size_t)m * Tt + t) * Hh + u], hn);
    }
}

extern "C" void kernel_launch(void* const* d_in, const int* in_sizes, int n_in,
                              void* d_out, int out_size) {
    const float* x  = (const float*)d_in[0];
    const float* A  = (const float*)d_in[1];
    const float* Wx = (const float*)d_in[2];
    const float* Wh = (const float*)d_in[3];
    const float* Wa = (const float*)d_in[4];
    const float* b  = (const float*)d_in[5];
    float* out = (float*)d_out;

    cudaFuncSetAttribute(gates_mma_kernel, cudaFuncAttributeMaxDynamicSharedMemorySize, NSTG * STB);
    cudaFuncSetAttribute(xproj_kernel, cudaFuncAttributeMaxDynamicSharedMemorySize, NSTG * STB);
    cudaFuncSetAttribute(attn_fused_kernel, cudaFuncAttributeMaxDynamicSharedMemorySize, ATT_SMEM);

    permute_kernel<<<2048, 256>>>(Wx, Wh, Wa, b);
    xsplit_kernel<<<4096, 256>>>(x);
    init_kernel<<<Nn, 256>>>(A);
    xproj_kernel<<<dim3(G4 / 32, MX / 128), 256, NSTG * STB>>>();
    for (int t = 0; t < Tt; t++) {
        attn_fused_kernel<<<Nn, 1024, ATT_SMEM>>>(A, t);
        gates_mma_kernel<<<G4 / 32, 256, NSTG * STB>>>(out, t);
    }
}

// round 11
// speedup vs baseline: 1.5318x; 1.5318x over previous
#include <cuda_runtime.h>
#include <cuda_bf16.h>
#include <math.h>
#include <stdint.h>

#define Nn 128
#define Tt 256
#define Dd 1024
#define Hh 1024
#define G4 4096
#define Pp 196
#define KR 2048   // recurrent K: [h | attn]
#define MX (Nn * Tt)

// ================= device scratch (static) =================
__device__ __align__(16) __nv_bfloat16 g_Wxh[(size_t)G4 * Dd];
__device__ __align__(16) __nv_bfloat16 g_Wxl[(size_t)G4 * Dd];
__device__ __align__(16) __nv_bfloat16 g_Wfh[(size_t)G4 * KR];
__device__ __align__(16) __nv_bfloat16 g_Wfl[(size_t)G4 * KR];
__device__ __align__(16) __nv_bfloat16 g_xh[(size_t)MX * Dd];
__device__ __align__(16) __nv_bfloat16 g_xl[(size_t)MX * Dd];
__device__ float g_xp[(size_t)MX * G4];
__device__ __align__(16) __nv_bfloat16 g_Abf[(size_t)Nn * Hh * Pp];  // bf16 A for scores
__device__ __align__(16) __nv_bfloat16 g_acth[(size_t)Nn * KR];
__device__ __align__(16) __nv_bfloat16 g_actl[(size_t)Nn * KR];
__device__ float g_bf[G4];
__device__ float g_hnewT[Hh * Nn];
__device__ float g_cT[Hh * Nn];
__device__ float g_sp[Nn][8][Pp];

// ================= helpers =================
__device__ __forceinline__ uint32_t smem_u32(const void* p) {
    uint32_t a;
    asm("{ .reg .u64 t; cvta.to.shared.u64 t, %1; cvt.u32.u64 %0, t; }" : "=r"(a) : "l"(p));
    return a;
}
__device__ __forceinline__ void cp16(uint32_t dst, const void* src) {
    asm volatile("cp.async.cg.shared.global [%0], [%1], 16;" :: "r"(dst), "l"(src));
}
__device__ __forceinline__ void cpcommit() { asm volatile("cp.async.commit_group;" ::: "memory"); }
template <int N> __device__ __forceinline__ void cpwait() {
    asm volatile("cp.async.wait_group %0;" :: "n"(N) : "memory");
}
__device__ __forceinline__ void ldsm_x4(uint32_t& r0, uint32_t& r1, uint32_t& r2, uint32_t& r3,
                                        uint32_t addr) {
    asm volatile("ldmatrix.sync.aligned.m8n8.x4.shared.b16 {%0,%1,%2,%3}, [%4];"
                 : "=r"(r0), "=r"(r1), "=r"(r2), "=r"(r3) : "r"(addr));
}
__device__ __forceinline__ void mma16816(float* d, const uint32_t* a, const uint32_t* b) {
    asm volatile(
        "mma.sync.aligned.m16n8k16.row.col.f32.bf16.bf16.f32 "
        "{%0,%1,%2,%3}, {%4,%5,%6,%7}, {%8,%9}, {%0,%1,%2,%3};"
        : "+f"(d[0]), "+f"(d[1]), "+f"(d[2]), "+f"(d[3])
        : "r"(a[0]), "r"(a[1]), "r"(a[2]), "r"(a[3]), "r"(b[0]), "r"(b[1]));
}
#define SWZ128(o) ((o) ^ (((o) >> 3) & 0x70))

__device__ __forceinline__ void bf16split(float v, __nv_bfloat16* hi, __nv_bfloat16* lo) {
    __nv_bfloat16 h = __float2bfloat16(v);
    *hi = h;
    *lo = __float2bfloat16(v - __bfloat162float(h));
}

// ================= one-time kernels =================
__global__ __launch_bounds__(256) void permute_kernel(
    const float* __restrict__ Wx, const float* __restrict__ Wh,
    const float* __restrict__ Wa, const float* __restrict__ b) {
    size_t total = (size_t)G4 * 3072;
    size_t stride = (size_t)gridDim.x * blockDim.x;
    for (size_t idx = (size_t)blockIdx.x * blockDim.x + threadIdx.x; idx < total; idx += stride) {
        int j = (int)(idx / 3072);
        int k = (int)(idx - (size_t)j * 3072);
        int src = (j & 3) * 1024 + (j >> 2);
        __nv_bfloat16 hi, lo;
        if (k < 1024) {
            bf16split(Wx[(size_t)k * G4 + src], &hi, &lo);
            g_Wxh[(size_t)j * Dd + k] = hi;
            g_Wxl[(size_t)j * Dd + k] = lo;
        } else {
            float v = (k < 2048) ? Wh[(size_t)(k - 1024) * G4 + src]
                                 : Wa[(size_t)(k - 2048) * G4 + src];
            bf16split(v, &hi, &lo);
            g_Wfh[(size_t)j * KR + (k - 1024)] = hi;
            g_Wfl[(size_t)j * KR + (k - 1024)] = lo;
        }
        if (k == 0) g_bf[j] = b[src];
    }
}

__global__ __launch_bounds__(256) void xsplit_kernel(const float* __restrict__ x) {
    size_t total = (size_t)MX * Dd;
    size_t stride = (size_t)gridDim.x * blockDim.x;
    for (size_t i = (size_t)blockIdx.x * blockDim.x + threadIdx.x; i < total; i += stride) {
        __nv_bfloat16 hi, lo;
        bf16split(x[i], &hi, &lo);
        g_xh[i] = hi;
        g_xl[i] = lo;
    }
}

__global__ __launch_bounds__(256) void a2bf_kernel(const float* __restrict__ A) {
    size_t total = (size_t)Nn * Hh * Pp;
    size_t stride = (size_t)gridDim.x * blockDim.x;
    for (size_t i = (size_t)blockIdx.x * blockDim.x + threadIdx.x; i < total; i += stride)
        g_Abf[i] = __float2bfloat16(A[i]);
}

__global__ __launch_bounds__(256) void init_kernel(const float* __restrict__ A) {
    int n = blockIdx.x;
    for (int u = threadIdx.x; u < Hh; u += blockDim.x) {
        const float4* r = (const float4*)(A + ((size_t)n * Hh + u) * Pp);
        float s = 0.f;
#pragma unroll
        for (int i = 0; i < 49; i++) {
            float4 v = r[i];
            s += v.x + v.y + v.z + v.w;
        }
        float m = s * (1.f / 196.f);
        g_hnewT[u * Nn + n] = m;
        g_cT[u * Nn + n] = m;
    }
}

// ================= generic split-bf16x3 mma mainloop (KC=64, SW128) =================
#define KC 64
#define STB 40960
#define NSTG 3

__device__ __forceinline__ void load_chunk_g(
    int tid, int c, char* buf,
    const __nv_bfloat16* Ah, const __nv_bfloat16* Al, int lda,
    const __nv_bfloat16* Bh, const __nv_bfloat16* Bl, int ldb) {
    uint32_t sbase = smem_u32(buf);
#pragma unroll
    for (int it = 0; it < 4; it++) {
        int id = tid + it * 256;           // 0..1023 : 128 rows x 8 16B-chunks
        int m = id >> 3, kc = id & 7;
        uint32_t off = SWZ128((uint32_t)m * 128 + (uint32_t)kc * 16);
        size_t gidx = (size_t)m * lda + (size_t)c * KC + kc * 8;
        cp16(sbase + off, Ah + gidx);
        cp16(sbase + 16384 + off, Al + gidx);
    }
    {
        int nrow = tid >> 3, kc = tid & 7;  // 256 = 32 rows x 8 chunks
        uint32_t off = SWZ128((uint32_t)nrow * 128 + (uint32_t)kc * 16);
        size_t gidx = (size_t)nrow * ldb + (size_t)c * KC + kc * 8;
        cp16(sbase + 32768 + off, Bh + gidx);
        cp16(sbase + 36864 + off, Bl + gidx);
    }
    cpcommit();
}

__device__ __forceinline__ void mma_mainloop(
    int tid, char* dsm, float acc[4][4], int nch,
    const __nv_bfloat16* Ah, const __nv_bfloat16* Al, int lda,
    const __nv_bfloat16* Bh, const __nv_bfloat16* Bl, int ldb) {
    int w = tid >> 5, lane = tid & 31;
    load_chunk_g(tid, 0, dsm, Ah, Al, lda, Bh, Bl, ldb);
    load_chunk_g(tid, 1, dsm + STB, Ah, Al, lda, Bh, Bl, ldb);
    for (int c = 0; c < nch; c++) {
        if (c + 1 < nch) cpwait<1>(); else cpwait<0>();
        __syncthreads();
        uint32_t sbase = smem_u32(dsm + (c % NSTG) * STB);
        int arow = w * 16 + (lane & 15);
#pragma unroll
        for (int ks = 0; ks < 4; ks++) {
            int ak = ks * 16 + ((lane & 16) ? 8 : 0);
            uint32_t aoff = SWZ128((uint32_t)arow * 128 + (uint32_t)ak * 2);
            uint32_t ah[4], al[4];
            ldsm_x4(ah[0], ah[1], ah[2], ah[3], sbase + aoff);
            ldsm_x4(al[0], al[1], al[2], al[3], sbase + 16384 + aoff);
            uint32_t bh[8], bl[8];
            int bk = ks * 16 + ((lane & 8) ? 8 : 0);
#pragma unroll
            for (int jj = 0; jj < 2; jj++) {
                int nrow = jj * 16 + ((lane & 16) ? 8 : 0) + (lane & 7);
                uint32_t boff = SWZ128((uint32_t)nrow * 128 + (uint32_t)bk * 2);
                ldsm_x4(bh[4 * jj], bh[4 * jj + 1], bh[4 * jj + 2], bh[4 * jj + 3],
                        sbase + 32768 + boff);
                ldsm_x4(bl[4 * jj], bl[4 * jj + 1], bl[4 * jj + 2], bl[4 * jj + 3],
                        sbase + 36864 + boff);
            }
#pragma unroll
            for (int j = 0; j < 4; j++) {
                mma16816(acc[j], ah, &bh[2 * j]);
                mma16816(acc[j], ah, &bl[2 * j]);
                mma16816(acc[j], al, &bh[2 * j]);
            }
        }
        if (c + 2 < nch)
            load_chunk_g(tid, c + 2, dsm + ((c + 2) % NSTG) * STB, Ah, Al, lda, Bh, Bl, ldb);
    }
}

// ================= one-time: xproj = x @ Wx + b =================
__global__ __launch_bounds__(256) void xproj_kernel() {
    extern __shared__ __align__(1024) char dsm[];
    int tid = threadIdx.x;
    int w = tid >> 5, lane = tid & 31;
    int j0 = blockIdx.x * 32;
    int m0 = blockIdx.y * 128;

    float acc[4][4];
#pragma unroll
    for (int j = 0; j < 4; j++)
#pragma unroll
        for (int r = 0; r < 4; r++) acc[j][r] = 0.f;

    mma_mainloop(tid, dsm, acc, Dd / KC,
                 g_xh + (size_t)m0 * Dd, g_xl + (size_t)m0 * Dd, Dd,
                 g_Wxh + (size_t)j0 * Dd, g_Wxl + (size_t)j0 * Dd, Dd);

    int row0 = m0 + w * 16 + (lane >> 2);
#pragma unroll
    for (int j = 0; j < 4; j++) {
        int col = j0 + j * 8 + (lane & 3) * 2;
        float2 bb = *(const float2*)&g_bf[col];
        *(float2*)&g_xp[(size_t)row0 * G4 + col] = make_float2(acc[j][0] + bb.x, acc[j][1] + bb.y);
        *(float2*)&g_xp[(size_t)(row0 + 8) * G4 + col] = make_float2(acc[j][2] + bb.x, acc[j][3] + bb.y);
    }
}

// ================= scores partial: grid (8,128); bf16 A; commits h split =================
__global__ __launch_bounds__(256) void scores_kernel(int t) {
    int uc = blockIdx.x;
    int n = (t & 1) ? (Nn - 1 - (int)blockIdx.y) : (int)blockIdx.y;  // zigzag by t
    int tid = threadIdx.x;
    int u0 = uc * 128;
    __shared__ float hsh[128];

    if (tid < 128) {
        float hv = g_hnewT[(u0 + tid) * Nn + n];
        __nv_bfloat16 hi, lo;
        bf16split(hv, &hi, &lo);
        g_acth[(size_t)n * KR + u0 + tid] = hi;
        g_actl[(size_t)n * KR + u0 + tid] = lo;
        hsh[tid] = hv;
    }
    __syncthreads();

    if (tid < Pp) {
        const __nv_bfloat16* ap = g_Abf + ((size_t)n * Hh + u0) * Pp + tid;
        float acc = 0.f;
#pragma unroll 8
        for (int u = 0; u < 128; u++) {
            acc += hsh[u] * __bfloat162float(ap[(size_t)u * Pp]);
        }
        g_sp[n][uc][tid] = acc;
    }
}

// ================= attn: softmax + weighted sum (fp32 A, zigzag) =================
__global__ __launch_bounds__(256) void attnsum_kernel(const float* __restrict__ A, int t) {
    int uc = blockIdx.x;
    int n = (t & 1) ? (Nn - 1 - (int)blockIdx.y) : (int)blockIdx.y;  // zigzag by t
    int tid = threadIdx.x;
    __shared__ __align__(16) float w[Pp];
    __shared__ float red[256];

    float myscore = 0.f, s = -3.4e38f;
    if (tid < Pp) {
        float acc = 0.f;
#pragma unroll
        for (int q = 0; q < 8; q++) acc += g_sp[n][q][tid];
        myscore = acc * 0.03125f;
        s = myscore;
    }
    red[tid] = s;
    __syncthreads();
    for (int off = 128; off > 0; off >>= 1) {
        if (tid < off) red[tid] = fmaxf(red[tid], red[tid + off]);
        __syncthreads();
    }
    float mx = red[0];
    __syncthreads();
    float e = (tid < Pp) ? expf(myscore - mx) : 0.f;
    red[tid] = e;
    __syncthreads();
    for (int off = 128; off > 0; off >>= 1) {
        if (tid < off) red[tid] += red[tid + off];
        __syncthreads();
    }
    float inv = 1.f / red[0];
    if (tid < Pp) w[tid] = e * inv;
    __syncthreads();

    int u = uc * 256 + tid;
    const float4* Ar = (const float4*)(A + ((size_t)n * Hh + u) * Pp);
    float acc = 0.f;
#pragma unroll
    for (int i = 0; i < 49; i++) {
        float4 av = Ar[i];
        float4 wv = *(const float4*)&w[4 * i];
        acc += av.x * wv.x + av.y * wv.y + av.z * wv.z + av.w * wv.w;
    }
    __nv_bfloat16 hi, lo;
    bf16split(acc, &hi, &lo);
    g_acth[(size_t)n * KR + 1024 + u] = hi;
    g_actl[(size_t)n * KR + 1024 + u] = lo;
}

// ================= gates: [h|attn]@Wf + xproj_t, fused LSTM =================
__global__ __launch_bounds__(256) void gates_mma_kernel(float* __restrict__ out, int t) {
    extern __shared__ __align__(1024) char dsm[];
    int tid = threadIdx.x;
    int w = tid >> 5, lane = tid & 31;
    int j0 = blockIdx.x * 32;

    float acc[4][4];
    {
        int row0 = w * 16 + (lane >> 2);
#pragma unroll
        for (int j = 0; j < 4; j++) {
            int col = j0 + j * 8 + (lane & 3) * 2;
            float2 v0 = __ldcs((const float2*)&g_xp[((size_t)row0 * Tt + t) * G4 + col]);
            float2 v1 = __ldcs((const float2*)&g_xp[((size_t)(row0 + 8) * Tt + t) * G4 + col]);
            acc[j][0] = v0.x; acc[j][1] = v0.y; acc[j][2] = v1.x; acc[j][3] = v1.y;
        }
    }

    mma_mainloop(tid, dsm, acc, KR / KC,
                 g_acth, g_actl, KR,
                 g_Wfh + (size_t)j0 * KR, g_Wfl + (size_t)j0 * KR, KR);

    int q = lane & 3;
    int rbase = w * 16 + (lane >> 2);
#pragma unroll
    for (int j = 0; j < 4; j++) {
        float e0 = __shfl_xor_sync(0xffffffff, acc[j][0], 1);
        float e1 = __shfl_xor_sync(0xffffffff, acc[j][1], 1);
        float e2 = __shfl_xor_sync(0xffffffff, acc[j][2], 1);
        float e3 = __shfl_xor_sync(0xffffffff, acc[j][3], 1);
        int u = blockIdx.x * 8 + 2 * j + (q >> 1);
        int m;
        float ai, af, ao, ag;
        if ((q & 1) == 0) {
            m = rbase;
            ai = acc[j][0]; af = acc[j][1]; ao = e0; ag = e1;
        } else {
            m = rbase + 8;
            ai = e2; af = e3; ao = acc[j][2]; ag = acc[j][3];
        }
        float ig = 1.f / (1.f + expf(-ai));
        float fg = 1.f / (1.f + expf(-af));
        float og = 1.f / (1.f + expf(-ao));
        float gg = tanhf(ag);
        float cn = fg * g_cT[u * Nn + m] + ig * gg;
        float hn = og * tanhf(cn);
        g_cT[u * Nn + m] = cn;
        g_hnewT[u * Nn + m] = hn;
        __stcs(&out[((size_t)m * Tt + t) * Hh + u], hn);
    }
}

extern "C" void kernel_launch(void* const* d_in, const int* in_sizes, int n_in,
                              void* d_out, int out_size) {
    const float* x  = (const float*)d_in[0];
    const float* A  = (const float*)d_in[1];
    const float* Wx = (const float*)d_in[2];
    const float* Wh = (const float*)d_in[3];
    const float* Wa = (const float*)d_in[4];
    const float* b  = (const float*)d_in[5];
    float* out = (float*)d_out;

    cudaFuncSetAttribute(gates_mma_kernel, cudaFuncAttributeMaxDynamicSharedMemorySize, NSTG * STB);
    cudaFuncSetAttribute(xproj_kernel, cudaFuncAttributeMaxDynamicSharedMemorySize, NSTG * STB);

    permute_kernel<<<2048, 256>>>(Wx, Wh, Wa, b);
    xsplit_kernel<<<4096, 256>>>(x);
    a2bf_kernel<<<4096, 256>>>(A);
    init_kernel<<<Nn, 256>>>(A);
    xproj_kernel<<<dim3(G4 / 32, MX / 128), 256, NSTG * STB>>>();
    for (int t = 0; t < Tt; t++) {
        scores_kernel<<<dim3(8, Nn), 256>>>(t);
        attnsum_kernel<<<dim3(4, Nn), 256>>>(A, t);
        gates_mma_kernel<<<G4 / 32, 256, NSTG * STB>>>(out, t);
    }
}

// round 12
// speedup vs baseline: 1.8852x; 1.2307x over previous
#include <cuda_runtime.h>
#include <cuda_bf16.h>
#include <math.h>
#include <stdint.h>

#define Nn 128
#define Tt 256
#define Dd 1024
#define Hh 1024
#define G4 4096
#define Pp 196
#define KR 2048   // recurrent K: [h | attn]
#define MX (Nn * Tt)

// ================= device scratch (static) =================
__device__ __align__(16) __nv_bfloat16 g_Wxh[(size_t)G4 * Dd];
__device__ __align__(16) __nv_bfloat16 g_Wxl[(size_t)G4 * Dd];
__device__ __align__(16) __nv_bfloat16 g_Wfh[(size_t)G4 * KR];
__device__ __align__(16) __nv_bfloat16 g_Wfl[(size_t)G4 * KR];
__device__ __align__(16) __nv_bfloat16 g_xh[(size_t)MX * Dd];
__device__ __align__(16) __nv_bfloat16 g_xl[(size_t)MX * Dd];
__device__ float g_xp[(size_t)MX * G4];
__device__ __align__(16) __nv_bfloat16 g_Abf[(size_t)Nn * Hh * Pp];  // bf16 A (both passes)
__device__ __align__(16) __nv_bfloat16 g_acth[(size_t)Nn * KR];
__device__ __align__(16) __nv_bfloat16 g_actl[(size_t)Nn * KR];
__device__ float g_bf[G4];
__device__ float g_hnewT[Hh * Nn];
__device__ float g_cT[Hh * Nn];
__device__ float g_sp[Nn][8][Pp];

// ================= helpers =================
__device__ __forceinline__ uint32_t smem_u32(const void* p) {
    uint32_t a;
    asm("{ .reg .u64 t; cvta.to.shared.u64 t, %1; cvt.u32.u64 %0, t; }" : "=r"(a) : "l"(p));
    return a;
}
__device__ __forceinline__ void cp16(uint32_t dst, const void* src) {
    asm volatile("cp.async.cg.shared.global [%0], [%1], 16;" :: "r"(dst), "l"(src));
}
__device__ __forceinline__ void cpcommit() { asm volatile("cp.async.commit_group;" ::: "memory"); }
template <int N> __device__ __forceinline__ void cpwait() {
    asm volatile("cp.async.wait_group %0;" :: "n"(N) : "memory");
}
__device__ __forceinline__ void ldsm_x4(uint32_t& r0, uint32_t& r1, uint32_t& r2, uint32_t& r3,
                                        uint32_t addr) {
    asm volatile("ldmatrix.sync.aligned.m8n8.x4.shared.b16 {%0,%1,%2,%3}, [%4];"
                 : "=r"(r0), "=r"(r1), "=r"(r2), "=r"(r3) : "r"(addr));
}
__device__ __forceinline__ void mma16816(float* d, const uint32_t* a, const uint32_t* b) {
    asm volatile(
        "mma.sync.aligned.m16n8k16.row.col.f32.bf16.bf16.f32 "
        "{%0,%1,%2,%3}, {%4,%5,%6,%7}, {%8,%9}, {%0,%1,%2,%3};"
        : "+f"(d[0]), "+f"(d[1]), "+f"(d[2]), "+f"(d[3])
        : "r"(a[0]), "r"(a[1]), "r"(a[2]), "r"(a[3]), "r"(b[0]), "r"(b[1]));
}
#define SWZ128(o) ((o) ^ (((o) >> 3) & 0x70))

__device__ __forceinline__ void bf16split(float v, __nv_bfloat16* hi, __nv_bfloat16* lo) {
    __nv_bfloat16 h = __float2bfloat16(v);
    *hi = h;
    *lo = __float2bfloat16(v - __bfloat162float(h));
}

// ================= one-time kernels =================
__global__ __launch_bounds__(256) void permute_kernel(
    const float* __restrict__ Wx, const float* __restrict__ Wh,
    const float* __restrict__ Wa, const float* __restrict__ b) {
    size_t total = (size_t)G4 * 3072;
    size_t stride = (size_t)gridDim.x * blockDim.x;
    for (size_t idx = (size_t)blockIdx.x * blockDim.x + threadIdx.x; idx < total; idx += stride) {
        int j = (int)(idx / 3072);
        int k = (int)(idx - (size_t)j * 3072);
        int src = (j & 3) * 1024 + (j >> 2);
        __nv_bfloat16 hi, lo;
        if (k < 1024) {
            bf16split(Wx[(size_t)k * G4 + src], &hi, &lo);
            g_Wxh[(size_t)j * Dd + k] = hi;
            g_Wxl[(size_t)j * Dd + k] = lo;
        } else {
            float v = (k < 2048) ? Wh[(size_t)(k - 1024) * G4 + src]
                                 : Wa[(size_t)(k - 2048) * G4 + src];
            bf16split(v, &hi, &lo);
            g_Wfh[(size_t)j * KR + (k - 1024)] = hi;
            g_Wfl[(size_t)j * KR + (k - 1024)] = lo;
        }
        if (k == 0) g_bf[j] = b[src];
    }
}

__global__ __launch_bounds__(256) void xsplit_kernel(const float* __restrict__ x) {
    size_t total = (size_t)MX * Dd;
    size_t stride = (size_t)gridDim.x * blockDim.x;
    for (size_t i = (size_t)blockIdx.x * blockDim.x + threadIdx.x; i < total; i += stride) {
        __nv_bfloat16 hi, lo;
        bf16split(x[i], &hi, &lo);
        g_xh[i] = hi;
        g_xl[i] = lo;
    }
}

__global__ __launch_bounds__(256) void a2bf_kernel(const float* __restrict__ A) {
    size_t total = (size_t)Nn * Hh * Pp;
    size_t stride = (size_t)gridDim.x * blockDim.x;
    for (size_t i = (size_t)blockIdx.x * blockDim.x + threadIdx.x; i < total; i += stride)
        g_Abf[i] = __float2bfloat16(A[i]);
}

__global__ __launch_bounds__(256) void init_kernel(const float* __restrict__ A) {
    int n = blockIdx.x;
    for (int u = threadIdx.x; u < Hh; u += blockDim.x) {
        const float4* r = (const float4*)(A + ((size_t)n * Hh + u) * Pp);
        float s = 0.f;
#pragma unroll
        for (int i = 0; i < 49; i++) {
            float4 v = r[i];
            s += v.x + v.y + v.z + v.w;
        }
        float m = s * (1.f / 196.f);
        g_hnewT[u * Nn + n] = m;
        g_cT[u * Nn + n] = m;
    }
}

// ================= generic split-bf16x3 mma mainloop (KC=64, SW128) =================
#define KC 64
#define STB 40960
#define NSTG 3

__device__ __forceinline__ void load_chunk_g(
    int tid, int c, char* buf,
    const __nv_bfloat16* Ah, const __nv_bfloat16* Al, int lda,
    const __nv_bfloat16* Bh, const __nv_bfloat16* Bl, int ldb) {
    uint32_t sbase = smem_u32(buf);
#pragma unroll
    for (int it = 0; it < 4; it++) {
        int id = tid + it * 256;           // 0..1023 : 128 rows x 8 16B-chunks
        int m = id >> 3, kc = id & 7;
        uint32_t off = SWZ128((uint32_t)m * 128 + (uint32_t)kc * 16);
        size_t gidx = (size_t)m * lda + (size_t)c * KC + kc * 8;
        cp16(sbase + off, Ah + gidx);
        cp16(sbase + 16384 + off, Al + gidx);
    }
    {
        int nrow = tid >> 3, kc = tid & 7;  // 256 = 32 rows x 8 chunks
        uint32_t off = SWZ128((uint32_t)nrow * 128 + (uint32_t)kc * 16);
        size_t gidx = (size_t)nrow * ldb + (size_t)c * KC + kc * 8;
        cp16(sbase + 32768 + off, Bh + gidx);
        cp16(sbase + 36864 + off, Bl + gidx);
    }
    cpcommit();
}

__device__ __forceinline__ void mma_mainloop(
    int tid, char* dsm, float acc[4][4], int nch,
    const __nv_bfloat16* Ah, const __nv_bfloat16* Al, int lda,
    const __nv_bfloat16* Bh, const __nv_bfloat16* Bl, int ldb) {
    int w = tid >> 5, lane = tid & 31;
    load_chunk_g(tid, 0, dsm, Ah, Al, lda, Bh, Bl, ldb);
    load_chunk_g(tid, 1, dsm + STB, Ah, Al, lda, Bh, Bl, ldb);
    for (int c = 0; c < nch; c++) {
        if (c + 1 < nch) cpwait<1>(); else cpwait<0>();
        __syncthreads();
        uint32_t sbase = smem_u32(dsm + (c % NSTG) * STB);
        int arow = w * 16 + (lane & 15);
#pragma unroll
        for (int ks = 0; ks < 4; ks++) {
            int ak = ks * 16 + ((lane & 16) ? 8 : 0);
            uint32_t aoff = SWZ128((uint32_t)arow * 128 + (uint32_t)ak * 2);
            uint32_t ah[4], al[4];
            ldsm_x4(ah[0], ah[1], ah[2], ah[3], sbase + aoff);
            ldsm_x4(al[0], al[1], al[2], al[3], sbase + 16384 + aoff);
            uint32_t bh[8], bl[8];
            int bk = ks * 16 + ((lane & 8) ? 8 : 0);
#pragma unroll
            for (int jj = 0; jj < 2; jj++) {
                int nrow = jj * 16 + ((lane & 16) ? 8 : 0) + (lane & 7);
                uint32_t boff = SWZ128((uint32_t)nrow * 128 + (uint32_t)bk * 2);
                ldsm_x4(bh[4 * jj], bh[4 * jj + 1], bh[4 * jj + 2], bh[4 * jj + 3],
                        sbase + 32768 + boff);
                ldsm_x4(bl[4 * jj], bl[4 * jj + 1], bl[4 * jj + 2], bl[4 * jj + 3],
                        sbase + 36864 + boff);
            }
#pragma unroll
            for (int j = 0; j < 4; j++) {
                mma16816(acc[j], ah, &bh[2 * j]);
                mma16816(acc[j], ah, &bl[2 * j]);
                mma16816(acc[j], al, &bh[2 * j]);
            }
        }
        if (c + 2 < nch)
            load_chunk_g(tid, c + 2, dsm + ((c + 2) % NSTG) * STB, Ah, Al, lda, Bh, Bl, ldb);
    }
}

// ================= one-time: xproj = x @ Wx + b =================
__global__ __launch_bounds__(256) void xproj_kernel() {
    extern __shared__ __align__(1024) char dsm[];
    int tid = threadIdx.x;
    int w = tid >> 5, lane = tid & 31;
    int j0 = blockIdx.x * 32;
    int m0 = blockIdx.y * 128;

    float acc[4][4];
#pragma unroll
    for (int j = 0; j < 4; j++)
#pragma unroll
        for (int r = 0; r < 4; r++) acc[j][r] = 0.f;

    mma_mainloop(tid, dsm, acc, Dd / KC,
                 g_xh + (size_t)m0 * Dd, g_xl + (size_t)m0 * Dd, Dd,
                 g_Wxh + (size_t)j0 * Dd, g_Wxl + (size_t)j0 * Dd, Dd);

    int row0 = m0 + w * 16 + (lane >> 2);
#pragma unroll
    for (int j = 0; j < 4; j++) {
        int col = j0 + j * 8 + (lane & 3) * 2;
        float2 bb = *(const float2*)&g_bf[col];
        *(float2*)&g_xp[(size_t)row0 * G4 + col] = make_float2(acc[j][0] + bb.x, acc[j][1] + bb.y);
        *(float2*)&g_xp[(size_t)(row0 + 8) * G4 + col] = make_float2(acc[j][2] + bb.x, acc[j][3] + bb.y);
    }
}

// ================= scores partial: grid (8,128); bf16 A; commits h split =================
__global__ __launch_bounds__(256) void scores_kernel(int t) {
    int uc = blockIdx.x;
    int n = (t & 1) ? (Nn - 1 - (int)blockIdx.y) : (int)blockIdx.y;  // zigzag by t
    int tid = threadIdx.x;
    int u0 = uc * 128;
    __shared__ float hsh[128];

    if (tid < 128) {
        float hv = g_hnewT[(u0 + tid) * Nn + n];
        __nv_bfloat16 hi, lo;
        bf16split(hv, &hi, &lo);
        g_acth[(size_t)n * KR + u0 + tid] = hi;
        g_actl[(size_t)n * KR + u0 + tid] = lo;
        hsh[tid] = hv;
    }
    __syncthreads();

    if (tid < Pp) {
        const __nv_bfloat16* ap = g_Abf + ((size_t)n * Hh + u0) * Pp + tid;
        float acc = 0.f;
#pragma unroll 8
        for (int u = 0; u < 128; u++) {
            acc += hsh[u] * __bfloat162float(ap[(size_t)u * Pp]);
        }
        g_sp[n][uc][tid] = acc;
    }
}

// ================= attn: softmax + weighted sum (bf16 A, zigzag) =================
__global__ __launch_bounds__(256) void attnsum_kernel(int t) {
    int uc = blockIdx.x;
    int n = (t & 1) ? (Nn - 1 - (int)blockIdx.y) : (int)blockIdx.y;  // zigzag by t
    int tid = threadIdx.x;
    __shared__ __align__(16) float w[Pp + 2];
    __shared__ float red[256];

    float myscore = 0.f, s = -3.4e38f;
    if (tid < Pp) {
        float acc = 0.f;
#pragma unroll
        for (int q = 0; q < 8; q++) acc += g_sp[n][q][tid];
        myscore = acc * 0.03125f;
        s = myscore;
    }
    red[tid] = s;
    __syncthreads();
    for (int off = 128; off > 0; off >>= 1) {
        if (tid < off) red[tid] = fmaxf(red[tid], red[tid + off]);
        __syncthreads();
    }
    float mx = red[0];
    __syncthreads();
    float e = (tid < Pp) ? expf(myscore - mx) : 0.f;
    red[tid] = e;
    __syncthreads();
    for (int off = 128; off > 0; off >>= 1) {
        if (tid < off) red[tid] += red[tid + off];
        __syncthreads();
    }
    float inv = 1.f / red[0];
    if (tid < Pp) w[tid] = e * inv;
    if (tid < 2) w[Pp + tid] = 0.f;
    __syncthreads();

    // attn[u] = Abf[n,u,:] . w   (98 x 4B bf16x2 loads, row = 392B)
    int u = uc * 256 + tid;
    const __nv_bfloat162* Ar = (const __nv_bfloat162*)(g_Abf + ((size_t)n * Hh + u) * Pp);
    float acc = 0.f;
#pragma unroll
    for (int i = 0; i < 98; i++) {
        float2 av = __bfloat1622float2(Ar[i]);
        acc += av.x * w[2 * i] + av.y * w[2 * i + 1];
    }
    __nv_bfloat16 hi, lo;
    bf16split(acc, &hi, &lo);
    g_acth[(size_t)n * KR + 1024 + u] = hi;
    g_actl[(size_t)n * KR + 1024 + u] = lo;
}

// ================= gates: [h|attn]@Wf + xproj_t, fused LSTM =================
__global__ __launch_bounds__(256) void gates_mma_kernel(float* __restrict__ out, int t) {
    extern __shared__ __align__(1024) char dsm[];
    int tid = threadIdx.x;
    int w = tid >> 5, lane = tid & 31;
    int j0 = blockIdx.x * 32;

    float acc[4][4];
    {
        int row0 = w * 16 + (lane >> 2);
#pragma unroll
        for (int j = 0; j < 4; j++) {
            int col = j0 + j * 8 + (lane & 3) * 2;
            float2 v0 = __ldcs((const float2*)&g_xp[((size_t)row0 * Tt + t) * G4 + col]);
            float2 v1 = __ldcs((const float2*)&g_xp[((size_t)(row0 + 8) * Tt + t) * G4 + col]);
            acc[j][0] = v0.x; acc[j][1] = v0.y; acc[j][2] = v1.x; acc[j][3] = v1.y;
        }
    }

    mma_mainloop(tid, dsm, acc, KR / KC,
                 g_acth, g_actl, KR,
                 g_Wfh + (size_t)j0 * KR, g_Wfl + (size_t)j0 * KR, KR);

    int q = lane & 3;
    int rbase = w * 16 + (lane >> 2);
#pragma unroll
    for (int j = 0; j < 4; j++) {
        float e0 = __shfl_xor_sync(0xffffffff, acc[j][0], 1);
        float e1 = __shfl_xor_sync(0xffffffff, acc[j][1], 1);
        float e2 = __shfl_xor_sync(0xffffffff, acc[j][2], 1);
        float e3 = __shfl_xor_sync(0xffffffff, acc[j][3], 1);
        int u = blockIdx.x * 8 + 2 * j + (q >> 1);
        int m;
        float ai, af, ao, ag;
        if ((q & 1) == 0) {
            m = rbase;
            ai = acc[j][0]; af = acc[j][1]; ao = e0; ag = e1;
        } else {
            m = rbase + 8;
            ai = e2; af = e3; ao = acc[j][2]; ag = acc[j][3];
        }
        float ig = 1.f / (1.f + expf(-ai));
        float fg = 1.f / (1.f + expf(-af));
        float og = 1.f / (1.f + expf(-ao));
        float gg = tanhf(ag);
        float cn = fg * g_cT[u * Nn + m] + ig * gg;
        float hn = og * tanhf(cn);
        g_cT[u * Nn + m] = cn;
        g_hnewT[u * Nn + m] = hn;
        __stcs(&out[((size_t)m * Tt + t) * Hh + u], hn);
    }
}

extern "C" void kernel_launch(void* const* d_in, const int* in_sizes, int n_in,
                              void* d_out, int out_size) {
    const float* x  = (const float*)d_in[0];
    const float* A  = (const float*)d_in[1];
    const float* Wx = (const float*)d_in[2];
    const float* Wh = (const float*)d_in[3];
    const float* Wa = (const float*)d_in[4];
    const float* b  = (const float*)d_in[5];
    float* out = (float*)d_out;

    cudaFuncSetAttribute(gates_mma_kernel, cudaFuncAttributeMaxDynamicSharedMemorySize, NSTG * STB);
    cudaFuncSetAttribute(xproj_kernel, cudaFuncAttributeMaxDynamicSharedMemorySize, NSTG * STB);

    permute_kernel<<<2048, 256>>>(Wx, Wh, Wa, b);
    xsplit_kernel<<<4096, 256>>>(x);
    a2bf_kernel<<<4096, 256>>>(A);
    init_kernel<<<Nn, 256>>>(A);
    xproj_kernel<<<dim3(G4 / 32, MX / 128), 256, NSTG * STB>>>();
    for (int t = 0; t < Tt; t++) {
        scores_kernel<<<dim3(8, Nn), 256>>>(t);
        attnsum_kernel<<<dim3(4, Nn), 256>>>(t);
        gates_mma_kernel<<<G4 / 32, 256, NSTG * STB>>>(out, t);
    }
}